// round 5
// baseline (speedup 1.0000x reference)
#include <cuda_runtime.h>
#include <math.h>

#define NM 64
#define NA 24
#define NP 276          // divisible by 4 (critical for cp.async all-or-nothing chunks)
#define NPPAD 288
#define NT 6000
#define NTPAD 6016
#define NTPAD2 6048     // gemm2 t coverage (63*96)
#define QV 0.22360679774997896f
#define KE 0.016666666666666666f

#define G1_TT 94        // t-tiles of 64
#define G1_KS 3         // gemm1 k-splits (18 tiles of 16 -> 6 each)
#define G2_PT 3         // p-tiles of 128 (PPAD 384)
#define G2_KS 63        // t-splits, chunk 96
#define G2_NKT 12       // 12 k-tiles of 8 per chunk
#define G2_PPAD 384

typedef unsigned long long u64;

// ---------------- static device scratch ----------------
__device__ float g_qxs[NM * NP];
__device__ float g_xs3[NM * NP];
__device__ float g_nq[NM];
__device__ float g_qxsTd[NPPAD * 128];         // qxs transposed + duplicated [p][2m]
__device__ float g_nt[NTPAD];
__device__ float g_ct[NTPAD];
__device__ float g_S1p[G1_KS * NM * NTPAD];
__device__ float g_S2p[G1_KS * NM * NTPAD];
__device__ float g_aT[NTPAD2 * 128];           // (q a) transposed + dup [t][2m]
__device__ float g_bT[NTPAD2 * 128];           // b transposed + dup
__device__ float g_Ep[G1_TT * NM];
__device__ float g_sa[G1_TT * NM];
__device__ float g_F2[G2_KS * NM * G2_PPAD];

__device__ __forceinline__ void ffma2(u64& c, u64 a, u64 b) {
    asm("fma.rn.f32x2 %0, %1, %2, %0;" : "+l"(c) : "l"(a), "l"(b));
}
__device__ __forceinline__ float2 upk(u64 v) {
    float2 f;
    asm("mov.b64 {%0, %1}, %2;" : "=f"(f.x), "=f"(f.y) : "l"(v));
    return f;
}
__device__ __forceinline__ void cp16(void* smem, const void* gptr, int bytes) {
    unsigned s = (unsigned)__cvta_generic_to_shared(smem);
    asm volatile("cp.async.ca.shared.global [%0], [%1], 16, %2;\n"
                 :: "r"(s), "l"(gptr), "r"(bytes));
}
__device__ __forceinline__ void cp_commit() {
    asm volatile("cp.async.commit_group;\n" ::: "memory");
}
__device__ __forceinline__ void cp_wait0() {
    asm volatile("cp.async.wait_group 0;\n" ::: "memory");
}

__device__ __forceinline__ void pair_ij(int p, int& i, int& j) {
    int ii = (int)((1.0f + sqrtf(1.0f + 8.0f * (float)p)) * 0.5f);
    while (ii * (ii - 1) / 2 > p) ii--;
    while ((ii + 1) * ii / 2 <= p) ii++;
    i = ii;
    j = p - ii * (ii - 1) / 2;
}

// ---------------- fused prep ----------------
__global__ void prep_kernel(const float* __restrict__ Rs,
                            const float* __restrict__ xt,
                            const float* __restrict__ jx) {
    const int tid = threadIdx.x;
    if (blockIdx.x < NM) {
        __shared__ float red[256];
        const int m = blockIdx.x;
        float ssum = 0.0f;
        #pragma unroll
        for (int rep = 0; rep < 2; rep++) {
            int p = tid + 256 * rep;
            if (p < NP) {
                int i, j;
                pair_ij(p, i, j);
                float dx = Rs[(m * NA + i) * 3 + 0] - Rs[(m * NA + j) * 3 + 0];
                float dy = Rs[(m * NA + i) * 3 + 1] - Rs[(m * NA + j) * 3 + 1];
                float dz = Rs[(m * NA + i) * 3 + 2] - Rs[(m * NA + j) * 3 + 2];
                float d = sqrtf(dx * dx + dy * dy + dz * dz);
                float xs = 1.0f / d;
                float qv = QV * xs;
                g_qxs[m * NP + p] = qv;
                g_xs3[m * NP + p] = xs * xs * xs;
                *(float2*)&g_qxsTd[p * 128 + 2 * m] = make_float2(qv, qv);
                ssum += qv * qv;
            } else if (p < NPPAD) {
                *(float2*)&g_qxsTd[p * 128 + 2 * m] = make_float2(0.0f, 0.0f);
            }
        }
        red[tid] = ssum;
        __syncthreads();
        if (tid < 32) {
            float s = red[tid];
            #pragma unroll
            for (int k = 1; k < 8; k++) s += red[tid + 32 * k];
            #pragma unroll
            for (int o = 16; o > 0; o >>= 1) s += __shfl_xor_sync(0xffffffffu, s, o);
            if (tid == 0) g_nq[m] = s;
        }
        return;
    }
    int w = ((blockIdx.x - NM) * blockDim.x + tid) >> 5;
    int lane = tid & 31;
    if (w >= NTPAD) return;
    if (w >= NT) {
        if (lane == 0) { g_nt[w] = 0.0f; g_ct[w] = 0.0f; }
        return;
    }
    const float* xr = xt + (size_t)w * NP;
    const float* jr = jx + (size_t)w * NP;
    float sn = 0.0f, sc = 0.0f;
    #pragma unroll
    for (int k = 0; k < 9; k++) {
        int p = lane + 32 * k;
        if (p < NP) {
            float x = xr[p];
            sn = fmaf(x, x, sn);
            sc = fmaf(x, jr[p], sc);
        }
    }
    #pragma unroll
    for (int o = 16; o > 0; o >>= 1) {
        sn += __shfl_xor_sync(0xffffffffu, sn, o);
        sc += __shfl_xor_sync(0xffffffffu, sc, o);
    }
    if (lane == 0) {
        g_nt[w] = QV * QV * sn;
        g_ct[w] = QV * sc;
    }
}

// ---------------- GEMM1 (8m x 4t frags, cp.async A, reg-staged B) ----------------
__global__ __launch_bounds__(128)
void gemm1p_kernel(const float* __restrict__ xt, const float* __restrict__ jx) {
    __shared__ float As[2][16 * 128];   // dup A [k][2m]
    __shared__ float Bx[2][16 * 68];    // [k][t]
    __shared__ float Bj[2][16 * 68];

    const int tid = threadIdx.x;
    const int tx = tid & 15;            // 4 t at 4*tx
    const int ty = tid >> 4;            // 8 m at 8*ty
    const int t0 = blockIdx.x * 64;
    const int ks = blockIdx.y;
    const int NKT = 6;

    const int lbt = tid >> 1;           // t row 0..63
    const int half = tid & 1;           // k-group half

    u64 acc1[8][2], acc2[8][2];
    #pragma unroll
    for (int i = 0; i < 8; i++) { acc1[i][0] = acc1[i][1] = 0ull; acc2[i][0] = acc2[i][1] = 0ull; }

    float4 xv[2], jv[2];

    auto cpA = [&](int kt, int buf) {
        int k0 = ks * 96 + kt * 16;
        #pragma unroll
        for (int c = 0; c < 4; c++) {
            int idx = tid + 128 * c;
            int row = idx >> 5, col = idx & 31;
            cp16(&As[buf][row * 128 + col * 4], &g_qxsTd[(k0 + row) * 128 + col * 4], 16);
        }
        cp_commit();
    };
    auto ldgB = [&](int kt) {
        int k0 = ks * 96 + kt * 16;
        int tg = t0 + lbt;
        #pragma unroll
        for (int c = 0; c < 2; c++) {
            int g = 2 * half + c;
            int kk = k0 + 4 * g;
            xv[c] = make_float4(0.f, 0.f, 0.f, 0.f);
            jv[c] = make_float4(0.f, 0.f, 0.f, 0.f);
            if (tg < NT && kk < NP) {
                xv[c] = *(const float4*)&xt[(size_t)tg * NP + kk];
                jv[c] = *(const float4*)&jx[(size_t)tg * NP + kk];
            }
        }
    };
    auto stsB = [&](int buf) {
        #pragma unroll
        for (int c = 0; c < 2; c++) {
            int g = 2 * half + c;
            Bx[buf][(4 * g + 0) * 68 + lbt] = xv[c].x;
            Bx[buf][(4 * g + 1) * 68 + lbt] = xv[c].y;
            Bx[buf][(4 * g + 2) * 68 + lbt] = xv[c].z;
            Bx[buf][(4 * g + 3) * 68 + lbt] = xv[c].w;
            Bj[buf][(4 * g + 0) * 68 + lbt] = jv[c].x;
            Bj[buf][(4 * g + 1) * 68 + lbt] = jv[c].y;
            Bj[buf][(4 * g + 2) * 68 + lbt] = jv[c].z;
            Bj[buf][(4 * g + 3) * 68 + lbt] = jv[c].w;
        }
    };

    // prologue
    ldgB(0);
    cpA(0, 0);
    stsB(0);
    ldgB(1);
    cp_wait0();
    __syncthreads();

    for (int kt = 0; kt < NKT; kt++) {
        const int cur = kt & 1;
        if (kt + 1 < NKT) {
            stsB(cur ^ 1);
            cpA(kt + 1, cur ^ 1);
        }
        if (kt + 2 < NKT) ldgB(kt + 2);

        #pragma unroll
        for (int k = 0; k < 16; k++) {
            ulonglong2 q0 = *(const ulonglong2*)&As[cur][k * 128 + 16 * ty];
            ulonglong2 q1 = *(const ulonglong2*)&As[cur][k * 128 + 16 * ty + 4];
            ulonglong2 q2 = *(const ulonglong2*)&As[cur][k * 128 + 16 * ty + 8];
            ulonglong2 q3 = *(const ulonglong2*)&As[cur][k * 128 + 16 * ty + 12];
            ulonglong2 X = *(const ulonglong2*)&Bx[cur][k * 68 + 4 * tx];
            ulonglong2 J = *(const ulonglong2*)&Bj[cur][k * 68 + 4 * tx];
            u64 Ap[8] = {q0.x, q0.y, q1.x, q1.y, q2.x, q2.y, q3.x, q3.y};
            #pragma unroll
            for (int mi = 0; mi < 8; mi++) {
                ffma2(acc1[mi][0], Ap[mi], X.x);
                ffma2(acc1[mi][1], Ap[mi], X.y);
                ffma2(acc2[mi][0], Ap[mi], J.x);
                ffma2(acc2[mi][1], Ap[mi], J.y);
            }
        }
        if (kt + 1 < NKT) cp_wait0();
        __syncthreads();
    }

    const int m0 = ty * 8;
    const int tb = t0 + 4 * tx;
    #pragma unroll
    for (int mi = 0; mi < 8; mi++) {
        float2 a0 = upk(acc1[mi][0]);
        float2 a1 = upk(acc1[mi][1]);
        float2 b0 = upk(acc2[mi][0]);
        float2 b1 = upk(acc2[mi][1]);
        size_t off = ((size_t)ks * NM + (m0 + mi)) * NTPAD + tb;
        *(float4*)&g_S1p[off] = make_float4(a0.x, a0.y, a1.x, a1.y);
        *(float4*)&g_S2p[off] = make_float4(b0.x, b0.y, b1.x, b1.y);
    }
}

// ---------------- epilogue: combine partials, transcendentals, write aT/bT dup ----------------
__global__ __launch_bounds__(256)
void ep_kernel() {
    __shared__ float red[2048];
    const int tid = threadIdx.x;
    const int tx = tid & 15;
    const int ty = tid >> 4;
    const int t0 = blockIdx.x * 64;
    const int m0 = ty * 4;
    const int tb = t0 + 4 * tx;

    float ntv[4], ctv[4];
    #pragma unroll
    for (int i = 0; i < 4; i++) { ntv[i] = g_nt[tb + i]; ctv[i] = g_ct[tb + i]; }

    float eloc[4], saloc[4];
    #pragma unroll
    for (int mi = 0; mi < 4; mi++) {
        float nqv = g_nq[m0 + mi];
        float4 s1 = make_float4(0.f, 0.f, 0.f, 0.f);
        float4 s2 = make_float4(0.f, 0.f, 0.f, 0.f);
        #pragma unroll
        for (int ks = 0; ks < G1_KS; ks++) {
            size_t off = ((size_t)ks * NM + (m0 + mi)) * NTPAD + tb;
            float4 u = *(const float4*)&g_S1p[off];
            float4 v = *(const float4*)&g_S2p[off];
            s1.x += u.x; s1.y += u.y; s1.z += u.z; s1.w += u.w;
            s2.x += v.x; s2.y += v.y; s2.z += v.z; s2.w += v.w;
        }
        float s1v[4] = {s1.x, s1.y, s1.z, s1.w};
        float s2v[4] = {s2.x, s2.y, s2.z, s2.w};
        float el = 0.0f, sl = 0.0f;
        #pragma unroll
        for (int j = 0; j < 4; j++) {
            float sq = fmaf(-2.0f * QV, s1v[j], nqv + ntv[j]);
            float xd = sqrtf(fmaxf(sq, 0.0f));
            float e  = KE * __expf(-xd);
            float dt = s2v[j] - ctv[j];
            float a  = e * dt;
            float b  = fmaf(e, xd, e);
            float qa = QV * a;
            *(float2*)&g_aT[(size_t)(tb + j) * 128 + 2 * (m0 + mi)] = make_float2(qa, qa);
            *(float2*)&g_bT[(size_t)(tb + j) * 128 + 2 * (m0 + mi)] = make_float2(b, b);
            el = fmaf(b, dt, el);
            sl += a;
        }
        eloc[mi] = el; saloc[mi] = sl;
    }

    float* Es = red;
    float* Ss = red + 1024;
    #pragma unroll
    for (int mi = 0; mi < 4; mi++) {
        Es[(m0 + mi) * 16 + tx] = eloc[mi];
        Ss[(m0 + mi) * 16 + tx] = saloc[mi];
    }
    __syncthreads();
    if (tid < 64) {
        float se = 0.0f, ss = 0.0f;
        #pragma unroll
        for (int x = 0; x < 16; x++) { se += Es[tid * 16 + x]; ss += Ss[tid * 16 + x]; }
        g_Ep[blockIdx.x * NM + tid] = se;
        g_sa[blockIdx.x * NM + tid] = ss;
    }
}

// ---------------- GEMM2 (8m x 8p frags, all cp.async): F2 = -((qa)@xst + b@Jx) ----------------
__global__ __launch_bounds__(128)
void gemm2_kernel(const float* __restrict__ xt, const float* __restrict__ jx) {
    __shared__ float Aa[2][8 * 128];    // dup [t][2m]
    __shared__ float Ab[2][8 * 128];
    __shared__ float Bx[2][8 * 128];    // [t][p]
    __shared__ float Bj[2][8 * 128];

    const int tid = threadIdx.x;
    const int tx = tid & 15;            // p: 4*tx and 64+4*tx
    const int ty = tid >> 4;            // 8 m at 8*ty
    const int p0 = blockIdx.x * 128;
    const int t0 = blockIdx.y * 96;

    u64 acc[8][4];
    #pragma unroll
    for (int i = 0; i < 8; i++) { acc[i][0] = acc[i][1] = acc[i][2] = acc[i][3] = 0ull; }

    auto cp_tile = [&](int kt, int buf) {
        int tt0 = t0 + kt * 8;
        #pragma unroll
        for (int c = 0; c < 2; c++) {
            int idx = tid + 128 * c;
            int row = idx >> 5, col4 = (idx & 31) * 4;
            // A matrices (always valid: g_aT/g_bT sized & zeroed to 6048)
            cp16(&Aa[buf][row * 128 + col4], &g_aT[(size_t)(tt0 + row) * 128 + col4], 16);
            cp16(&Ab[buf][row * 128 + col4], &g_bT[(size_t)(tt0 + row) * 128 + col4], 16);
            // B matrices with zfill for t/p padding
            int tg = tt0 + row;
            int pc = p0 + col4;
            int ok = (tg < NT && pc < NP) ? 16 : 0;
            const float* xs_ = ok ? &xt[(size_t)tg * NP + pc] : xt;
            const float* js_ = ok ? &jx[(size_t)tg * NP + pc] : jx;
            cp16(&Bx[buf][row * 128 + col4], xs_, ok);
            cp16(&Bj[buf][row * 128 + col4], js_, ok);
        }
        cp_commit();
    };

    cp_tile(0, 0);
    cp_wait0();
    __syncthreads();

    for (int kt = 0; kt < G2_NKT; kt++) {
        const int cur = kt & 1;
        if (kt + 1 < G2_NKT) cp_tile(kt + 1, cur ^ 1);

        #pragma unroll
        for (int k = 0; k < 8; k++) {
            {
                ulonglong2 q0 = *(const ulonglong2*)&Aa[cur][k * 128 + 16 * ty];
                ulonglong2 q1 = *(const ulonglong2*)&Aa[cur][k * 128 + 16 * ty + 4];
                ulonglong2 q2 = *(const ulonglong2*)&Aa[cur][k * 128 + 16 * ty + 8];
                ulonglong2 q3 = *(const ulonglong2*)&Aa[cur][k * 128 + 16 * ty + 12];
                ulonglong2 X0 = *(const ulonglong2*)&Bx[cur][k * 128 + 4 * tx];
                ulonglong2 X1 = *(const ulonglong2*)&Bx[cur][k * 128 + 64 + 4 * tx];
                u64 Ap[8] = {q0.x, q0.y, q1.x, q1.y, q2.x, q2.y, q3.x, q3.y};
                #pragma unroll
                for (int mi = 0; mi < 8; mi++) {
                    ffma2(acc[mi][0], Ap[mi], X0.x);
                    ffma2(acc[mi][1], Ap[mi], X0.y);
                    ffma2(acc[mi][2], Ap[mi], X1.x);
                    ffma2(acc[mi][3], Ap[mi], X1.y);
                }
            }
            {
                ulonglong2 q0 = *(const ulonglong2*)&Ab[cur][k * 128 + 16 * ty];
                ulonglong2 q1 = *(const ulonglong2*)&Ab[cur][k * 128 + 16 * ty + 4];
                ulonglong2 q2 = *(const ulonglong2*)&Ab[cur][k * 128 + 16 * ty + 8];
                ulonglong2 q3 = *(const ulonglong2*)&Ab[cur][k * 128 + 16 * ty + 12];
                ulonglong2 J0 = *(const ulonglong2*)&Bj[cur][k * 128 + 4 * tx];
                ulonglong2 J1 = *(const ulonglong2*)&Bj[cur][k * 128 + 64 + 4 * tx];
                u64 Bp[8] = {q0.x, q0.y, q1.x, q1.y, q2.x, q2.y, q3.x, q3.y};
                #pragma unroll
                for (int mi = 0; mi < 8; mi++) {
                    ffma2(acc[mi][0], Bp[mi], J0.x);
                    ffma2(acc[mi][1], Bp[mi], J0.y);
                    ffma2(acc[mi][2], Bp[mi], J1.x);
                    ffma2(acc[mi][3], Bp[mi], J1.y);
                }
            }
        }
        if (kt + 1 < G2_NKT) cp_wait0();
        __syncthreads();
    }

    const int m0 = ty * 8;
    #pragma unroll
    for (int mi = 0; mi < 8; mi++) {
        float2 u0 = upk(acc[mi][0]);
        float2 u1 = upk(acc[mi][1]);
        float2 u2 = upk(acc[mi][2]);
        float2 u3 = upk(acc[mi][3]);
        size_t base = ((size_t)blockIdx.y * NM + (m0 + mi)) * G2_PPAD;
        *(float4*)&g_F2[base + p0 + 4 * tx]      = make_float4(-u0.x, -u0.y, -u1.x, -u1.y);
        *(float4*)&g_F2[base + p0 + 64 + 4 * tx] = make_float4(-u2.x, -u2.y, -u3.x, -u3.y);
    }
}

// ---------------- final ----------------
__global__ void final_kernel(const float* __restrict__ Rs, float* __restrict__ out) {
    __shared__ float Fxs[NP];
    __shared__ float ssa;
    const int m = blockIdx.x;
    const int tid = threadIdx.x;

    if (tid < 32) {
        float s = 0.0f;
        for (int b = tid; b < G1_TT; b += 32) s += g_sa[b * NM + m];
        #pragma unroll
        for (int o = 16; o > 0; o >>= 1) s += __shfl_xor_sync(0xffffffffu, s, o);
        if (tid == 0) ssa = s;
    } else if (tid < 64) {
        int l = tid - 32;
        float e = 0.0f;
        for (int b = l; b < G1_TT; b += 32) e += g_Ep[b * NM + m];
        #pragma unroll
        for (int o = 16; o > 0; o >>= 1) e += __shfl_xor_sync(0xffffffffu, e, o);
        if (l == 0) out[m] = e / QV;
    }
    __syncthreads();

    if (tid < NP) {
        float F = ssa * g_qxs[m * NP + tid];
        #pragma unroll 7
        for (int ks = 0; ks < G2_KS; ks++)
            F += g_F2[((size_t)ks * NM + m) * G2_PPAD + tid];
        Fxs[tid] = F * g_xs3[m * NP + tid];
    }
    __syncthreads();

    if (tid < NA * 3) {
        int a = tid / 3, c = tid % 3;
        float Ra = Rs[(m * NA + a) * 3 + c];
        float acc = 0.0f;
        #pragma unroll
        for (int bb = 0; bb < NA; bb++) {
            if (bb == a) continue;
            int hi = (a > bb) ? a : bb;
            int lo = (a > bb) ? bb : a;
            int p = hi * (hi - 1) / 2 + lo;
            float Rb = Rs[(m * NA + bb) * 3 + c];
            acc += (Rb - Ra) * Fxs[p];
        }
        out[NM + m * NA * 3 + tid] = acc;
    }
}

extern "C" void kernel_launch(void* const* d_in, const int* in_sizes, int n_in,
                              void* d_out, int out_size) {
    const float* Rs = (const float*)d_in[0];
    const float* xs_train = (const float*)d_in[1];
    const float* Jx = (const float*)d_in[2];
    float* out = (float*)d_out;

    prep_kernel<<<NM + NTPAD / 8, 256>>>(Rs, xs_train, Jx);
    gemm1p_kernel<<<dim3(G1_TT, G1_KS), 128>>>(xs_train, Jx);
    ep_kernel<<<G1_TT, 256>>>();
    gemm2_kernel<<<dim3(G2_PT, G2_KS), 128>>>(xs_train, Jx);
    final_kernel<<<NM, 288>>>(Rs, out);
}

// round 7
// speedup vs baseline: 1.0404x; 1.0404x over previous
#include <cuda_runtime.h>
#include <math.h>

#define NM 64
#define NA 24
#define NP 276
#define NPPAD 288
#define NT 6000
#define NTPAD 6016
#define QV 0.22360679774997896f
#define KE 0.016666666666666666f

#define G1_TT 47        // t-tiles of 128
#define G1_KS 6         // k-splits (48 k each, 3 k-tiles of 16)
#define G2_PT 3         // p-tiles of 128 (PPAD 384)
#define G2_KS 98        // t-splits, chunk 64 (8 k-tiles of 8)
#define G2_PPAD 384

typedef unsigned long long u64;

// ---------------- static device scratch ----------------
__device__ float g_qxs[NM * NP];
__device__ float g_xs3[NM * NP];
__device__ float g_nq[NM];
__device__ float g_qxsTd[NPPAD * 128];         // qxs transposed + dup [p][2m]
__device__ float g_nt[NTPAD];
__device__ float g_ct[NTPAD];
__device__ float g_S1p[G1_KS * NM * NTPAD];
__device__ float g_S2p[G1_KS * NM * NTPAD];
__device__ float g_aT[NTPAD * 128];            // (q a) transposed + dup [t][2m]
__device__ float g_bT[NTPAD * 128];
__device__ float g_Ep[94 * NM];
__device__ float g_sa[94 * NM];
__device__ float g_F2[G2_KS * NM * G2_PPAD];

__device__ __forceinline__ void ffma2(u64& c, u64 a, u64 b) {
    asm("fma.rn.f32x2 %0, %1, %2, %0;" : "+l"(c) : "l"(a), "l"(b));
}
__device__ __forceinline__ float2 upk(u64 v) {
    float2 f;
    asm("mov.b64 {%0, %1}, %2;" : "=f"(f.x), "=f"(f.y) : "l"(v));
    return f;
}
__device__ __forceinline__ void cp16(void* smem, const void* gptr, int bytes) {
    unsigned s = (unsigned)__cvta_generic_to_shared(smem);
    asm volatile("cp.async.ca.shared.global [%0], [%1], 16, %2;\n"
                 :: "r"(s), "l"(gptr), "r"(bytes));
}
__device__ __forceinline__ void cp_commit() {
    asm volatile("cp.async.commit_group;\n" ::: "memory");
}
__device__ __forceinline__ void cp_wait0() {
    asm volatile("cp.async.wait_group 0;\n" ::: "memory");
}

__device__ __forceinline__ void pair_ij(int p, int& i, int& j) {
    int ii = (int)((1.0f + sqrtf(1.0f + 8.0f * (float)p)) * 0.5f);
    while (ii * (ii - 1) / 2 > p) ii--;
    while ((ii + 1) * ii / 2 <= p) ii++;
    i = ii;
    j = p - ii * (ii - 1) / 2;
}

// ---------------- fused prep ----------------
__global__ void prep_kernel(const float* __restrict__ Rs,
                            const float* __restrict__ xt,
                            const float* __restrict__ jx) {
    const int tid = threadIdx.x;
    if (blockIdx.x < NM) {
        __shared__ float red[256];
        const int m = blockIdx.x;
        float ssum = 0.0f;
        #pragma unroll
        for (int rep = 0; rep < 2; rep++) {
            int p = tid + 256 * rep;
            if (p < NP) {
                int i, j;
                pair_ij(p, i, j);
                float dx = Rs[(m * NA + i) * 3 + 0] - Rs[(m * NA + j) * 3 + 0];
                float dy = Rs[(m * NA + i) * 3 + 1] - Rs[(m * NA + j) * 3 + 1];
                float dz = Rs[(m * NA + i) * 3 + 2] - Rs[(m * NA + j) * 3 + 2];
                float d = sqrtf(dx * dx + dy * dy + dz * dz);
                float xs = 1.0f / d;
                float qv = QV * xs;
                g_qxs[m * NP + p] = qv;
                g_xs3[m * NP + p] = xs * xs * xs;
                *(float2*)&g_qxsTd[p * 128 + 2 * m] = make_float2(qv, qv);
                ssum += qv * qv;
            } else if (p < NPPAD) {
                *(float2*)&g_qxsTd[p * 128 + 2 * m] = make_float2(0.0f, 0.0f);
            }
        }
        red[tid] = ssum;
        __syncthreads();
        if (tid < 32) {
            float s = red[tid];
            #pragma unroll
            for (int k = 1; k < 8; k++) s += red[tid + 32 * k];
            #pragma unroll
            for (int o = 16; o > 0; o >>= 1) s += __shfl_xor_sync(0xffffffffu, s, o);
            if (tid == 0) g_nq[m] = s;
        }
        return;
    }
    int w = ((blockIdx.x - NM) * blockDim.x + tid) >> 5;
    int lane = tid & 31;
    if (w >= NTPAD) return;
    if (w >= NT) {
        if (lane == 0) { g_nt[w] = 0.0f; g_ct[w] = 0.0f; }
        return;
    }
    const float* xr = xt + (size_t)w * NP;
    const float* jr = jx + (size_t)w * NP;
    float sn = 0.0f, sc = 0.0f;
    #pragma unroll
    for (int k = 0; k < 9; k++) {
        int p = lane + 32 * k;
        if (p < NP) {
            float x = xr[p];
            sn = fmaf(x, x, sn);
            sc = fmaf(x, jr[p], sc);
        }
    }
    #pragma unroll
    for (int o = 16; o > 0; o >>= 1) {
        sn += __shfl_xor_sync(0xffffffffu, sn, o);
        sc += __shfl_xor_sync(0xffffffffu, sc, o);
    }
    if (lane == 0) {
        g_nt[w] = QV * QV * sn;
        g_ct[w] = QV * sc;
    }
}

// ---------------- GEMM1: 256 thr, tile 64m x 128t, frag 8m x 4t ----------------
__global__ __launch_bounds__(256)
void gemm1p_kernel(const float* __restrict__ xt, const float* __restrict__ jx) {
    __shared__ float As[2][16 * 128];   // dup A [k][2m]
    __shared__ float Bx[2][16 * 132];   // [k][t]
    __shared__ float Bj[2][16 * 132];

    const int tid = threadIdx.x;
    const int tx = tid & 31;            // 4 t at t0+4*tx (covers 128 t)
    const int ty = tid >> 5;            // 8 m at 8*ty
    const int t0 = blockIdx.x * 128;
    const int ks = blockIdx.y;
    const int NKT = 3;                  // 3 k-tiles of 16 per split

    const int lbt = tid >> 1;           // B loader t row 0..127
    const int half = tid & 1;

    u64 acc1[8][2], acc2[8][2];
    #pragma unroll
    for (int i = 0; i < 8; i++) { acc1[i][0] = acc1[i][1] = 0ull; acc2[i][0] = acc2[i][1] = 0ull; }

    float4 xv[2], jv[2];

    auto cpA = [&](int kt, int buf) {
        int k0 = ks * 48 + kt * 16;
        #pragma unroll
        for (int c = 0; c < 2; c++) {
            int idx = tid + 256 * c;
            int row = idx >> 5, col = idx & 31;
            cp16(&As[buf][row * 128 + col * 4], &g_qxsTd[(k0 + row) * 128 + col * 4], 16);
        }
        cp_commit();
    };
    auto ldgB = [&](int kt) {
        int k0 = ks * 48 + kt * 16;
        int tg = t0 + lbt;
        #pragma unroll
        for (int c = 0; c < 2; c++) {
            int g = 2 * half + c;
            int kk = k0 + 4 * g;
            xv[c] = make_float4(0.f, 0.f, 0.f, 0.f);
            jv[c] = make_float4(0.f, 0.f, 0.f, 0.f);
            if (tg < NT && kk < NP) {
                xv[c] = *(const float4*)&xt[(size_t)tg * NP + kk];
                jv[c] = *(const float4*)&jx[(size_t)tg * NP + kk];
            }
        }
    };
    auto stsB = [&](int buf) {
        #pragma unroll
        for (int c = 0; c < 2; c++) {
            int g = 2 * half + c;
            Bx[buf][(4 * g + 0) * 132 + lbt] = xv[c].x;
            Bx[buf][(4 * g + 1) * 132 + lbt] = xv[c].y;
            Bx[buf][(4 * g + 2) * 132 + lbt] = xv[c].z;
            Bx[buf][(4 * g + 3) * 132 + lbt] = xv[c].w;
            Bj[buf][(4 * g + 0) * 132 + lbt] = jv[c].x;
            Bj[buf][(4 * g + 1) * 132 + lbt] = jv[c].y;
            Bj[buf][(4 * g + 2) * 132 + lbt] = jv[c].z;
            Bj[buf][(4 * g + 3) * 132 + lbt] = jv[c].w;
        }
    };

    ldgB(0);
    cpA(0, 0);
    stsB(0);
    ldgB(1);
    cp_wait0();
    __syncthreads();

    for (int kt = 0; kt < NKT; kt++) {
        const int cur = kt & 1;
        if (kt + 1 < NKT) {
            stsB(cur ^ 1);
            cpA(kt + 1, cur ^ 1);
        }
        if (kt + 2 < NKT) ldgB(kt + 2);

        #pragma unroll
        for (int k = 0; k < 16; k++) {
            ulonglong2 q0 = *(const ulonglong2*)&As[cur][k * 128 + 16 * ty];
            ulonglong2 q1 = *(const ulonglong2*)&As[cur][k * 128 + 16 * ty + 4];
            ulonglong2 q2 = *(const ulonglong2*)&As[cur][k * 128 + 16 * ty + 8];
            ulonglong2 q3 = *(const ulonglong2*)&As[cur][k * 128 + 16 * ty + 12];
            ulonglong2 X = *(const ulonglong2*)&Bx[cur][k * 132 + 4 * tx];
            ulonglong2 J = *(const ulonglong2*)&Bj[cur][k * 132 + 4 * tx];
            u64 Ap[8] = {q0.x, q0.y, q1.x, q1.y, q2.x, q2.y, q3.x, q3.y};
            #pragma unroll
            for (int mi = 0; mi < 8; mi++) {
                ffma2(acc1[mi][0], Ap[mi], X.x);
                ffma2(acc1[mi][1], Ap[mi], X.y);
                ffma2(acc2[mi][0], Ap[mi], J.x);
                ffma2(acc2[mi][1], Ap[mi], J.y);
            }
        }
        if (kt + 1 < NKT) cp_wait0();
        __syncthreads();
    }

    const int m0 = ty * 8;
    const int tb = t0 + 4 * tx;
    #pragma unroll
    for (int mi = 0; mi < 8; mi++) {
        float2 a0 = upk(acc1[mi][0]);
        float2 a1 = upk(acc1[mi][1]);
        float2 b0 = upk(acc2[mi][0]);
        float2 b1 = upk(acc2[mi][1]);
        size_t off = ((size_t)ks * NM + (m0 + mi)) * NTPAD + tb;
        *(float4*)&g_S1p[off] = make_float4(a0.x, a0.y, a1.x, a1.y);
        *(float4*)&g_S2p[off] = make_float4(b0.x, b0.y, b1.x, b1.y);
    }
}

// ---------------- epilogue ----------------
__global__ __launch_bounds__(256)
void ep_kernel() {
    __shared__ float red[2048];
    const int tid = threadIdx.x;
    const int tx = tid & 15;
    const int ty = tid >> 4;
    const int t0 = blockIdx.x * 64;
    const int m0 = ty * 4;
    const int tb = t0 + 4 * tx;

    float ntv[4], ctv[4];
    #pragma unroll
    for (int i = 0; i < 4; i++) { ntv[i] = g_nt[tb + i]; ctv[i] = g_ct[tb + i]; }

    float eloc[4], saloc[4];
    #pragma unroll
    for (int mi = 0; mi < 4; mi++) {
        float nqv = g_nq[m0 + mi];
        float4 s1 = make_float4(0.f, 0.f, 0.f, 0.f);
        float4 s2 = make_float4(0.f, 0.f, 0.f, 0.f);
        #pragma unroll
        for (int ks = 0; ks < G1_KS; ks++) {
            size_t off = ((size_t)ks * NM + (m0 + mi)) * NTPAD + tb;
            float4 u = *(const float4*)&g_S1p[off];
            float4 v = *(const float4*)&g_S2p[off];
            s1.x += u.x; s1.y += u.y; s1.z += u.z; s1.w += u.w;
            s2.x += v.x; s2.y += v.y; s2.z += v.z; s2.w += v.w;
        }
        float s1v[4] = {s1.x, s1.y, s1.z, s1.w};
        float s2v[4] = {s2.x, s2.y, s2.z, s2.w};
        float el = 0.0f, sl = 0.0f;
        #pragma unroll
        for (int j = 0; j < 4; j++) {
            float sq = fmaf(-2.0f * QV, s1v[j], nqv + ntv[j]);
            float xd = sqrtf(fmaxf(sq, 0.0f));
            float e  = KE * __expf(-xd);
            float dt = s2v[j] - ctv[j];
            float a  = e * dt;
            float b  = fmaf(e, xd, e);
            float qa = QV * a;
            *(float2*)&g_aT[(size_t)(tb + j) * 128 + 2 * (m0 + mi)] = make_float2(qa, qa);
            *(float2*)&g_bT[(size_t)(tb + j) * 128 + 2 * (m0 + mi)] = make_float2(b, b);
            el = fmaf(b, dt, el);
            sl += a;
        }
        eloc[mi] = el; saloc[mi] = sl;
    }

    float* Es = red;
    float* Ss = red + 1024;
    #pragma unroll
    for (int mi = 0; mi < 4; mi++) {
        Es[(m0 + mi) * 16 + tx] = eloc[mi];
        Ss[(m0 + mi) * 16 + tx] = saloc[mi];
    }
    __syncthreads();
    if (tid < 64) {
        float se = 0.0f, ss = 0.0f;
        #pragma unroll
        for (int x = 0; x < 16; x++) { se += Es[tid * 16 + x]; ss += Ss[tid * 16 + x]; }
        g_Ep[blockIdx.x * NM + tid] = se;
        g_sa[blockIdx.x * NM + tid] = ss;
    }
}

// ---------------- GEMM2: 256 thr, tile 64m x 128p, frag 4m x 8p ----------------
__global__ __launch_bounds__(256)
void gemm2_kernel(const float* __restrict__ xt, const float* __restrict__ jx) {
    __shared__ float Aa[2][8 * 128];    // dup [t][2m]
    __shared__ float Ab[2][8 * 128];
    __shared__ float Bx[2][8 * 128];    // [t][p]
    __shared__ float Bj[2][8 * 128];

    const int tid = threadIdx.x;
    const int tx = tid & 15;            // p: 4*tx and 64+4*tx
    const int ty = tid >> 4;            // 4 m at 4*ty
    const int p0 = blockIdx.x * 128;
    const int t0 = blockIdx.y * 64;
    const int NKT = 8;                  // 8 k-tiles of 8

    u64 acc[4][4];
    #pragma unroll
    for (int i = 0; i < 4; i++) { acc[i][0] = acc[i][1] = acc[i][2] = acc[i][3] = 0ull; }

    auto cp_tile = [&](int kt, int buf) {
        int tt0 = t0 + kt * 8;
        int row = tid >> 5, col4 = (tid & 31) * 4;
        int tg = tt0 + row;
        int okA = (tg < NTPAD) ? 16 : 0;
        const float* ap = okA ? &g_aT[(size_t)tg * 128 + col4] : g_aT;
        const float* bp = okA ? &g_bT[(size_t)tg * 128 + col4] : g_bT;
        cp16(&Aa[buf][row * 128 + col4], ap, okA);
        cp16(&Ab[buf][row * 128 + col4], bp, okA);
        int pc = p0 + col4;
        int okB = (tg < NT && pc < NP) ? 16 : 0;
        const float* xp = okB ? &xt[(size_t)tg * NP + pc] : xt;
        const float* jp = okB ? &jx[(size_t)tg * NP + pc] : jx;
        cp16(&Bx[buf][row * 128 + col4], xp, okB);
        cp16(&Bj[buf][row * 128 + col4], jp, okB);
        cp_commit();
    };

    cp_tile(0, 0);
    cp_wait0();
    __syncthreads();

    for (int kt = 0; kt < NKT; kt++) {
        const int cur = kt & 1;
        if (kt + 1 < NKT) cp_tile(kt + 1, cur ^ 1);

        #pragma unroll
        for (int k = 0; k < 8; k++) {
            ulonglong2 a01 = *(const ulonglong2*)&Aa[cur][k * 128 + 8 * ty];
            ulonglong2 a23 = *(const ulonglong2*)&Aa[cur][k * 128 + 8 * ty + 4];
            ulonglong2 b01 = *(const ulonglong2*)&Ab[cur][k * 128 + 8 * ty];
            ulonglong2 b23 = *(const ulonglong2*)&Ab[cur][k * 128 + 8 * ty + 4];
            ulonglong2 X0 = *(const ulonglong2*)&Bx[cur][k * 128 + 4 * tx];
            ulonglong2 X1 = *(const ulonglong2*)&Bx[cur][k * 128 + 64 + 4 * tx];
            ulonglong2 J0 = *(const ulonglong2*)&Bj[cur][k * 128 + 4 * tx];
            ulonglong2 J1 = *(const ulonglong2*)&Bj[cur][k * 128 + 64 + 4 * tx];
            u64 Ap[4] = {a01.x, a01.y, a23.x, a23.y};
            u64 Bp[4] = {b01.x, b01.y, b23.x, b23.y};
            #pragma unroll
            for (int mi = 0; mi < 4; mi++) {
                ffma2(acc[mi][0], Ap[mi], X0.x);
                ffma2(acc[mi][1], Ap[mi], X0.y);
                ffma2(acc[mi][2], Ap[mi], X1.x);
                ffma2(acc[mi][3], Ap[mi], X1.y);
            }
            #pragma unroll
            for (int mi = 0; mi < 4; mi++) {
                ffma2(acc[mi][0], Bp[mi], J0.x);
                ffma2(acc[mi][1], Bp[mi], J0.y);
                ffma2(acc[mi][2], Bp[mi], J1.x);
                ffma2(acc[mi][3], Bp[mi], J1.y);
            }
        }
        if (kt + 1 < NKT) cp_wait0();
        __syncthreads();
    }

    const int m0 = ty * 4;
    #pragma unroll
    for (int mi = 0; mi < 4; mi++) {
        float2 u0 = upk(acc[mi][0]);
        float2 u1 = upk(acc[mi][1]);
        float2 u2 = upk(acc[mi][2]);
        float2 u3 = upk(acc[mi][3]);
        size_t base = ((size_t)blockIdx.y * NM + (m0 + mi)) * G2_PPAD;
        *(float4*)&g_F2[base + p0 + 4 * tx]      = make_float4(-u0.x, -u0.y, -u1.x, -u1.y);
        *(float4*)&g_F2[base + p0 + 64 + 4 * tx] = make_float4(-u2.x, -u2.y, -u3.x, -u3.y);
    }
}

// ---------------- final ----------------
__global__ void final_kernel(const float* __restrict__ Rs, float* __restrict__ out) {
    __shared__ float Fxs[NP];
    __shared__ float ssa;
    const int m = blockIdx.x;
    const int tid = threadIdx.x;

    if (tid < 32) {
        float s = 0.0f;
        for (int b = tid; b < 94; b += 32) s += g_sa[b * NM + m];
        #pragma unroll
        for (int o = 16; o > 0; o >>= 1) s += __shfl_xor_sync(0xffffffffu, s, o);
        if (tid == 0) ssa = s;
    } else if (tid < 64) {
        int l = tid - 32;
        float e = 0.0f;
        for (int b = l; b < 94; b += 32) e += g_Ep[b * NM + m];
        #pragma unroll
        for (int o = 16; o > 0; o >>= 1) e += __shfl_xor_sync(0xffffffffu, e, o);
        if (l == 0) out[m] = e / QV;
    }
    __syncthreads();

    if (tid < NP) {
        float F = ssa * g_qxs[m * NP + tid];
        #pragma unroll 7
        for (int ks = 0; ks < G2_KS; ks++)
            F += g_F2[((size_t)ks * NM + m) * G2_PPAD + tid];
        Fxs[tid] = F * g_xs3[m * NP + tid];
    }
    __syncthreads();

    if (tid < NA * 3) {
        int a = tid / 3, c = tid % 3;
        float Ra = Rs[(m * NA + a) * 3 + c];
        float acc = 0.0f;
        #pragma unroll
        for (int bb = 0; bb < NA; bb++) {
            if (bb == a) continue;
            int hi = (a > bb) ? a : bb;
            int lo = (a > bb) ? bb : a;
            int p = hi * (hi - 1) / 2 + lo;
            float Rb = Rs[(m * NA + bb) * 3 + c];
            acc += (Rb - Ra) * Fxs[p];
        }
        out[NM + m * NA * 3 + tid] = acc;
    }
}

extern "C" void kernel_launch(void* const* d_in, const int* in_sizes, int n_in,
                              void* d_out, int out_size) {
    const float* Rs = (const float*)d_in[0];
    const float* xs_train = (const float*)d_in[1];
    const float* Jx = (const float*)d_in[2];
    float* out = (float*)d_out;

    prep_kernel<<<NM + NTPAD / 8, 256>>>(Rs, xs_train, Jx);
    gemm1p_kernel<<<dim3(G1_TT, G1_KS), 256>>>(xs_train, Jx);
    ep_kernel<<<94, 256>>>();
    gemm2_kernel<<<dim3(G2_PT, G2_KS), 256>>>(xs_train, Jx);
    final_kernel<<<NM, 288>>>(Rs, out);
}